// round 16
// baseline (speedup 1.0000x reference)
#include <cuda_runtime.h>
#include <cuda_fp16.h>
#include <math.h>
#include <stdint.h>

#define M_TRAIN 4096
#define M_TEST  16384
#define DIN     128
#define HID     1024
#define NTREES  16
#define NINT    31
#define NLEAF   32
#define NCLS    10
#define NSPLIT  (NTREES*NINT)        /* 496 */
#define SW_ROWS (NTREES*NINT*DIN)    /* 63488 */
#define LF_ROWS (NTREES*NLEAF*NCLS)  /* 5120 */
#define MV_ROWS (SW_ROWS + NSPLIT + LF_ROWS + NTREES)  /* 69120 */

/* ---------------- scratch (static device memory; no allocs) -------------- */
__device__ __half g_C1[M_TRAIN*HID];
__device__ __half g_C2[M_TRAIN*HID];
__device__ __half g_H1[M_TRAIN*HID];
__device__ __half g_Y2[M_TRAIN*HID];
__device__ __half g_Xtr[M_TRAIN*DIN];
__device__ __half g_W1[HID*DIN];
__device__ __half g_W2[HID*HID];
__device__ __half g_Xte[M_TEST*DIN];
__device__ __half g_SW[SW_ROWS];
__device__ float  g_part[64*HID];
__device__ float  g_ctx[HID];
__device__ float  g_sb[NSPLIT];
__device__ float  g_lf[LF_ROWS];
__device__ float  g_tw[NTREES];
__device__ float  g_W[LF_ROWS];
__device__ float  g_sink[32];

/* ------------------------------ PTX helpers ------------------------------ */
__device__ __forceinline__ uint32_t cvta_sm(const void* p) {
    return (uint32_t)__cvta_generic_to_shared(p);
}
__device__ __forceinline__ void cp16(uint32_t dst, const void* src, int sz) {
    asm volatile("cp.async.cg.shared.global [%0], [%1], 16, %2;\n"
                 :: "r"(dst), "l"(src), "r"(sz));
}
__device__ __forceinline__ void cp_commit() {
    asm volatile("cp.async.commit_group;\n");
}
__device__ __forceinline__ void ldsm4(unsigned& r0, unsigned& r1,
                                      unsigned& r2, unsigned& r3, uint32_t a) {
    asm volatile("ldmatrix.sync.aligned.m8n8.x4.shared.b16 {%0,%1,%2,%3}, [%4];"
                 : "=r"(r0), "=r"(r1), "=r"(r2), "=r"(r3) : "r"(a));
}
__device__ __forceinline__ void mma_f16(float c[4], unsigned a0, unsigned a1,
                                        unsigned a2, unsigned a3,
                                        unsigned b0, unsigned b1)
{
    asm volatile(
        "mma.sync.aligned.m16n8k16.row.col.f32.f16.f16.f32 "
        "{%0,%1,%2,%3}, {%4,%5,%6,%7}, {%8,%9}, {%0,%1,%2,%3};"
        : "+f"(c[0]), "+f"(c[1]), "+f"(c[2]), "+f"(c[3])
        : "r"(a0), "r"(a1), "r"(a2), "r"(a3), "r"(b0), "r"(b1));
}
__device__ __forceinline__ uint32_t swz(int r, int hb) {
    return (uint32_t)(r*64 + ((hb ^ ((r>>1)&3)) << 4));
}

/* ---------- ONE launch: convert all static inputs to fp16 ---------------- */
__global__ void cvt_all(const float* __restrict__ xtr, const float* __restrict__ w1,
                        const float* __restrict__ w2,  const float* __restrict__ xte,
                        __half* __restrict__ xtrh, __half* __restrict__ w1h,
                        __half* __restrict__ w2h,  __half* __restrict__ xteh)
{
    int b = blockIdx.x;
    const float* src;
    __half* dst;
    int base;
    if (b < 128)      { src = xtr; dst = xtrh; base = b; }
    else if (b < 160) { src = w1;  dst = w1h;  base = b - 128; }
    else if (b < 416) { src = w2;  dst = w2h;  base = b - 160; }
    else              { src = xte; dst = xteh; base = b - 416; }

    int i0 = base * 1024 + threadIdx.x;
    float4 v[4];
#pragma unroll
    for (int u = 0; u < 4; u++) v[u] = ((const float4*)src)[i0 + u*256];
#pragma unroll
    for (int u = 0; u < 4; u++) {
        int i = i0 + u*256;
        ((__half2*)dst)[i*2]   = __halves2half2(__float2half_rn(v[u].x),
                                                __float2half_rn(v[u].y));
        ((__half2*)dst)[i*2+1] = __halves2half2(__float2half_rn(v[u].z),
                                                __float2half_rn(v[u].w));
    }
}

/* ------ L2 prefetch of sw_w head (reverse order; loads kept by guard) ---- */
__global__ void prefetch_l2(const float4* __restrict__ w, float* __restrict__ sink,
                            int n4)
{
    int b = gridDim.x - 1 - blockIdx.x;              /* reverse: low addrs last */
    int i = b * (256*8) + threadIdx.x;
    float s = 0.f;
#pragma unroll
    for (int u = 0; u < 8; u++) {
        int idx = i + u*256;
        if (idx < n4) {
            float4 v = __ldg(&w[idx]);
            s += v.x + v.y + v.z + v.w;
        }
    }
    /* never-taken in practice; prevents load elision, race-free determinism */
    if (s == 1.23456789e+30f) sink[0] = s;
}

/* ---- 128x128 fp16 GEMM, 512 threads, 32x32 warp tiles, fp16 out --------- */
#define GSTAGE 16384
#define GNSTG  3

__global__ void __launch_bounds__(512, 2) gemm512(
    const __half* __restrict__ Ah, const __half* __restrict__ Bh,
    const float* __restrict__ bias, __half* __restrict__ C,
    int M, int N, int K)
{
    extern __shared__ char dynsm[];
    const uint32_t smem = cvta_sm(dynsm);
    const int tid = threadIdx.x, lane = tid & 31, warp = tid >> 5;
    const int g = lane >> 2, t = lane & 3;
    const int wm = warp & 3, wn = warp >> 2;
    const int m0 = blockIdx.y * 128, n0 = blockIdx.x * 128;

    float c[2][4][4];
#pragma unroll
    for (int i = 0; i < 2; i++)
#pragma unroll
        for (int j = 0; j < 4; j++)
#pragma unroll
            for (int r = 0; r < 4; r++) c[i][j][r] = 0.f;

    const int kIters = K >> 5;

    auto load_stage = [&](int buf, int k0) {
        uint32_t sb = smem + buf * GSTAGE;
        int r = tid >> 2, hb = tid & 3;
        uint32_t so = swz(r, hb);
        cp16(sb + so,        Ah + (size_t)(m0 + r) * K + k0 + hb*8, 16);
        cp16(sb + 8192 + so, Bh + (size_t)(n0 + r) * K + k0 + hb*8, 16);
    };

    auto compute = [&](int buf) {
        uint32_t sb = smem + buf * GSTAGE;
        const int rl = lane & 15;
        const int hx = lane >> 4;
#pragma unroll
        for (int s = 0; s < 2; s++) {
            const int hb = s*2 + hx;
            unsigned bf[4][2];
#pragma unroll
            for (int j2 = 0; j2 < 2; j2++) {
                int row = wn*32 + j2*16 + rl;
                unsigned r0, r1, r2, r3;
                ldsm4(r0, r1, r2, r3, sb + 8192 + swz(row, hb));
                bf[j2*2][0]=r0; bf[j2*2][1]=r2; bf[j2*2+1][0]=r1; bf[j2*2+1][1]=r3;
            }
#pragma unroll
            for (int i = 0; i < 2; i++) {
                int row = wm*32 + i*16 + rl;
                unsigned a0,a1,a2,a3;
                ldsm4(a0,a1,a2,a3, sb + swz(row, hb));
#pragma unroll
                for (int j = 0; j < 4; j++)
                    mma_f16(c[i][j], a0,a1,a2,a3, bf[j][0], bf[j][1]);
            }
        }
    };

    load_stage(0, 0);
    cp_commit();
    load_stage(1, 32);
    cp_commit();
    for (int it = 0; it < kIters; it++) {
        if (it + 1 < kIters)
            asm volatile("cp.async.wait_group 1;\n" ::: "memory");
        else
            asm volatile("cp.async.wait_group 0;\n" ::: "memory");
        __syncthreads();
        compute(it % GNSTG);
        if (it + 2 < kIters) {
            load_stage((it+2) % GNSTG, (it+2)*32);
            cp_commit();
        }
    }

#pragma unroll
    for (int i = 0; i < 2; i++) {
        int r0 = m0 + wm*32 + i*16 + g;
#pragma unroll
        for (int j = 0; j < 4; j++) {
            int col = n0 + wn*32 + j*8 + 2*t;
            float b0 = bias[col], b1 = bias[col+1];
            *(__half2*)&C[(size_t)r0     * N + col] =
                __halves2half2(__float2half_rn(c[i][j][0] + b0),
                               __float2half_rn(c[i][j][1] + b1));
            *(__half2*)&C[(size_t)(r0+8) * N + col] =
                __halves2half2(__float2half_rn(c[i][j][2] + b0),
                               __float2half_rn(c[i][j][3] + b1));
        }
    }
}

/* ==== FUSED dec GEMM + sigmoid + routing, 32-row CTA, occupancy 2 ======== */
#define DR_STAGE  34816
#define DR_SMEM   110592
#define TR_PITCH  513

__global__ void __launch_bounds__(512, 2) dec_route(
    const __half* __restrict__ Xte, const __half* __restrict__ SW,
    const float* __restrict__ sbias, const float* __restrict__ Wtab,
    float* __restrict__ out)
{
    extern __shared__ char dynsm[];
    const uint32_t smem = cvta_sm(dynsm);
    float* trans = (float*)dynsm;                     /* [32][513] */
    float* Wsh   = (float*)(dynsm + 69632);           /* [5120]    */
    float* pt    = (float*)(dynsm + 90112);           /* [32][16][10] */

    const int tid = threadIdx.x, lane = tid & 31, warp = tid >> 5;
    const int g = lane >> 2, t4 = lane & 3;
    const int wm = warp & 1, wn = warp >> 1;
    const int m0 = blockIdx.x * 32;

    for (int i = tid; i < LF_ROWS; i += 512) Wsh[i] = Wtab[i];

    float c[8][4];
#pragma unroll
    for (int j = 0; j < 8; j++)
#pragma unroll
        for (int r = 0; r < 4; r++) c[j][r] = 0.f;

    auto load_stage = [&](int buf, int k0) {
        uint32_t sb = smem + buf * DR_STAGE;
        if (tid < 128) {
            int r = tid >> 2, hb = tid & 3;
            cp16(sb + swz(r, hb), Xte + (size_t)(m0 + r) * DIN + k0 + hb*8, 16);
        }
#pragma unroll
        for (int x = 0; x < 4; x++) {
            int ch = tid + x*512;
            int r = ch >> 2, hb = ch & 3;
            int sz = (r < NSPLIT) ? 16 : 0;
            size_t gb = (size_t)(sz ? r : 0) * DIN + k0 + hb*8;
            cp16(sb + 2048 + swz(r, hb), SW + gb, sz);
        }
    };

    auto compute = [&](int buf) {
        uint32_t sb = smem + buf * DR_STAGE;
        const int rl = lane & 15, hx = lane >> 4;
#pragma unroll
        for (int s = 0; s < 2; s++) {
            const int hb = s*2 + hx;
            unsigned a0,a1,a2,a3;
            {
                int row = wm*16 + rl;
                ldsm4(a0,a1,a2,a3, sb + swz(row, hb));
            }
            unsigned bf[8][2];
#pragma unroll
            for (int j2 = 0; j2 < 4; j2++) {
                int row = wn*64 + j2*16 + rl;
                unsigned r0,r1,r2,r3;
                ldsm4(r0,r1,r2,r3, sb + 2048 + swz(row, hb));
                bf[j2*2][0]=r0; bf[j2*2][1]=r2;
                bf[j2*2+1][0]=r1; bf[j2*2+1][1]=r3;
            }
#pragma unroll
            for (int j = 0; j < 8; j++)
                mma_f16(c[j], a0,a1,a2,a3, bf[j][0], bf[j][1]);
        }
    };

    const int kIters = DIN >> 5;   /* 4 */
    load_stage(0, 0);
    cp_commit();
    load_stage(1, 32);
    cp_commit();
    for (int it = 0; it < kIters; it++) {
        if (it + 1 < kIters)
            asm volatile("cp.async.wait_group 1;\n" ::: "memory");
        else
            asm volatile("cp.async.wait_group 0;\n" ::: "memory");
        __syncthreads();
        compute(it & 1);
        __syncthreads();
        if (it + 2 < kIters) {
            load_stage(it & 1, (it+2)*32);
            cp_commit();
        }
    }

    __syncthreads();

    {
        int r0 = wm*16 + g, r1 = r0 + 8;
#pragma unroll
        for (int j = 0; j < 8; j++) {
            int col = wn*64 + j*8 + 2*t4;
            float b0 = (col     < NSPLIT) ? sbias[col]   : 0.f;
            float b1 = (col + 1 < NSPLIT) ? sbias[col+1] : 0.f;
            trans[r0*TR_PITCH + col]   = 1.f/(1.f + __expf(-(c[j][0] + b0)));
            trans[r0*TR_PITCH + col+1] = 1.f/(1.f + __expf(-(c[j][1] + b1)));
            trans[r1*TR_PITCH + col]   = 1.f/(1.f + __expf(-(c[j][2] + b0)));
            trans[r1*TR_PITCH + col+1] = 1.f/(1.f + __expf(-(c[j][3] + b1)));
        }
    }
    __syncthreads();

    {
        const int t = warp, r = lane;
        const float* d = &trans[r*TR_PITCH + t*NINT];
        float acc[NCLS];
#pragma unroll
        for (int cc = 0; cc < NCLS; cc++) acc[cc] = 0.f;
#pragma unroll
        for (int l = 0; l < NLEAF; l++) {
            float p = 1.f;
#pragma unroll
            for (int dd = 0; dd < 5; dd++) {
                int node = (1 << dd) - 1 + (l >> (5 - dd));
                int go   = (l >> (4 - dd)) & 1;
                float dv = d[node];
                p *= go ? dv : (1.f - dv);
            }
            const float* w = &Wsh[(t*NLEAF + l)*NCLS];
#pragma unroll
            for (int cc = 0; cc < NCLS; cc++) acc[cc] += p * w[cc];
        }
#pragma unroll
        for (int cc = 0; cc < NCLS; cc++) pt[(r*16 + t)*NCLS + cc] = acc[cc];
    }
    __syncthreads();

    if (tid < 32*NCLS) {
        int r = tid / NCLS, cc = tid % NCLS;
        float s = 0.f;
#pragma unroll
        for (int t = 0; t < 16; t++) s += pt[(r*16 + t)*NCLS + cc];
        out[(size_t)(m0 + r)*NCLS + cc] = s;
    }
}

/* ------------- LayerNorm + ReLU, fp16 in -> fp16 out ---------------------- */
__global__ void ln_relu_h(const __half* __restrict__ X, __half* __restrict__ Y,
                          const float* __restrict__ gg, const float* __restrict__ bb)
{
    const int row = blockIdx.x, tid = threadIdx.x;
    const uint4 raw = ((const uint4*)(X + (size_t)row * HID))[tid];
    const __half2* h2 = (const __half2*)&raw;
    float v[8];
#pragma unroll
    for (int k = 0; k < 4; k++) {
        float2 f = __half22float2(h2[k]);
        v[k*2] = f.x; v[k*2+1] = f.y;
    }
    float s = 0.f, q = 0.f;
#pragma unroll
    for (int k = 0; k < 8; k++) { s += v[k]; q += v[k]*v[k]; }
#pragma unroll
    for (int o = 16; o; o >>= 1) {
        s += __shfl_xor_sync(0xffffffffu, s, o);
        q += __shfl_xor_sync(0xffffffffu, q, o);
    }
    __shared__ float ss[4], qs[4];
    if ((tid & 31) == 0) { ss[tid >> 5] = s; qs[tid >> 5] = q; }
    __syncthreads();
    s = ss[0]+ss[1]+ss[2]+ss[3];
    q = qs[0]+qs[1]+qs[2]+qs[3];
    float mean = s * (1.f/HID);
    float inv  = rsqrtf(q * (1.f/HID) - mean*mean + 1e-5f);
    float4 g0 = ((const float4*)gg)[tid*2],   g1 = ((const float4*)gg)[tid*2+1];
    float4 b0 = ((const float4*)bb)[tid*2],   b1 = ((const float4*)bb)[tid*2+1];
    float gv[8] = {g0.x,g0.y,g0.z,g0.w,g1.x,g1.y,g1.z,g1.w};
    float bv[8] = {b0.x,b0.y,b0.z,b0.w,b1.x,b1.y,b1.z,b1.w};
    uint4 outp;
    __half2* o2 = (__half2*)&outp;
#pragma unroll
    for (int k = 0; k < 4; k++) {
        float y0 = fmaxf((v[k*2]   - mean)*inv*gv[k*2]   + bv[k*2],   0.f);
        float y1 = fmaxf((v[k*2+1] - mean)*inv*gv[k*2+1] + bv[k*2+1], 0.f);
        o2[k] = __halves2half2(__float2half_rn(y0), __float2half_rn(y1));
    }
    ((uint4*)(Y + (size_t)row * HID))[tid] = outp;
}

/* --------------------- column mean over rows -> ctx (fp16 in) ------------ */
__global__ void col_partial_h(const __half* __restrict__ X, float* __restrict__ part)
{
    int col2  = blockIdx.x * 256 + threadIdx.x;
    int chunk = blockIdx.y;
    float2 s = make_float2(0.f, 0.f);
    int r0 = chunk * 64;
    for (int r = r0; r < r0 + 64; r++) {
        float2 f = __half22float2(((const __half2*)(X + (size_t)r * HID))[col2]);
        s.x += f.x; s.y += f.y;
    }
    *(float2*)&part[(size_t)chunk * HID + col2*2] = s;
}
__global__ void col_final(const float* __restrict__ part, float* __restrict__ ctx)
{
    int col = blockIdx.x * 256 + threadIdx.x;
    float s = 0.f;
    for (int c = 0; c < 64; c++) s += part[(size_t)c * HID + col];
    ctx[col] = s * (1.f / M_TRAIN);
}

/* ---------- ONE launch: all hypernet matvecs (warp-id dispatch) ----------- */
__global__ void matvec_all(const float* __restrict__ sw_w, const float* __restrict__ sw_b,
                           const float* __restrict__ sb_w, const float* __restrict__ sb_b,
                           const float* __restrict__ lf_w, const float* __restrict__ lf_b,
                           const float* __restrict__ tw_w, const float* __restrict__ tw_b,
                           const float* __restrict__ ctx,
                           __half* __restrict__ swh,
                           float* __restrict__ sbo, float* __restrict__ lfo,
                           float* __restrict__ two)
{
    int gw   = (blockIdx.x * blockDim.x + threadIdx.x) >> 5;
    int lane = threadIdx.x & 31;
    if (gw >= MV_ROWS) return;
    const float *W, *bias;
    int row, mode;
    if (gw < SW_ROWS)                  { W=sw_w; bias=sw_b; row=gw;                    mode=0; }
    else if (gw < SW_ROWS+NSPLIT)      { W=sb_w; bias=sb_b; row=gw-SW_ROWS;            mode=1; }
    else if (gw < SW_ROWS+NSPLIT+LF_ROWS) { W=lf_w; bias=lf_b; row=gw-SW_ROWS-NSPLIT;  mode=2; }
    else                               { W=tw_w; bias=tw_b; row=gw-SW_ROWS-NSPLIT-LF_ROWS; mode=3; }

    const float4* w4 = (const float4*)(W + (size_t)row * HID);
    const float4* c4 = (const float4*)ctx;
    float s = 0.f;
#pragma unroll
    for (int i = 0; i < 8; i++) {
        float4 a = w4[lane + 32*i];
        float4 c = __ldg(&c4[lane + 32*i]);
        s += a.x*c.x + a.y*c.y + a.z*c.z + a.w*c.w;
    }
#pragma unroll
    for (int o = 16; o; o >>= 1) s += __shfl_xor_sync(0xffffffffu, s, o);
    if (lane == 0) {
        float v = s + bias[row];
        if (mode == 0)      swh[row] = __float2half_rn(v);
        else if (mode == 1) sbo[row] = v;
        else if (mode == 2) lfo[row] = v;
        else                two[row] = v;
    }
}

/* ---- fold tree_w softmax + leaf softmax into one table W[t,l,c] --------- */
__global__ void make_W(const float* __restrict__ tw, const float* __restrict__ lf,
                       float* __restrict__ Wout)
{
    __shared__ float tws[NTREES];
    int tid = threadIdx.x;
    if (tid == 0) {
        float mx = -1e30f;
        for (int i = 0; i < NTREES; i++) mx = fmaxf(mx, tw[i]);
        float e[NTREES], s = 0.f;
        for (int i = 0; i < NTREES; i++) { e[i] = expf(tw[i] - mx); s += e[i]; }
        for (int i = 0; i < NTREES; i++) tws[i] = e[i] / s;
    }
    __syncthreads();
    if (tid < NTREES * NLEAF) {
        const float* L = lf + tid * NCLS;
        float mx = -1e30f;
        for (int c = 0; c < NCLS; c++) mx = fmaxf(mx, L[c]);
        float e[NCLS], s = 0.f;
        for (int c = 0; c < NCLS; c++) { e[c] = expf(L[c] - mx); s += e[c]; }
        float scale = tws[tid >> 5] / s;
        for (int c = 0; c < NCLS; c++) Wout[tid * NCLS + c] = e[c] * scale;
    }
}

/* ------------------------------- launch ---------------------------------- */
extern "C" void kernel_launch(void* const* d_in, const int* in_sizes, int n_in,
                              void* d_out, int out_size)
{
    const float* X_train = (const float*)d_in[0];
    const float* X_test  = (const float*)d_in[1];
    const float* enc_w1  = (const float*)d_in[2];
    const float* enc_b1  = (const float*)d_in[3];
    const float* ln1_g   = (const float*)d_in[4];
    const float* ln1_b   = (const float*)d_in[5];
    const float* enc_w2  = (const float*)d_in[6];
    const float* enc_b2  = (const float*)d_in[7];
    const float* ln2_g   = (const float*)d_in[8];
    const float* ln2_b   = (const float*)d_in[9];
    const float* sw_w    = (const float*)d_in[10];
    const float* sw_b    = (const float*)d_in[11];
    const float* sb_w    = (const float*)d_in[12];
    const float* sb_b    = (const float*)d_in[13];
    const float* lf_w    = (const float*)d_in[14];
    const float* lf_b    = (const float*)d_in[15];
    const float* tw_w    = (const float*)d_in[16];
    const float* tw_b    = (const float*)d_in[17];

    float *part, *ctx, *sb, *lf, *tw, *W, *sink;
    __half *C1, *C2, *H1, *Y2, *Xtr, *W1, *W2, *Xte, *SW;
    cudaGetSymbolAddress((void**)&C1,   g_C1);
    cudaGetSymbolAddress((void**)&C2,   g_C2);
    cudaGetSymbolAddress((void**)&H1,   g_H1);
    cudaGetSymbolAddress((void**)&Y2,   g_Y2);
    cudaGetSymbolAddress((void**)&Xtr,  g_Xtr);
    cudaGetSymbolAddress((void**)&W1,   g_W1);
    cudaGetSymbolAddress((void**)&W2,   g_W2);
    cudaGetSymbolAddress((void**)&Xte,  g_Xte);
    cudaGetSymbolAddress((void**)&SW,   g_SW);
    cudaGetSymbolAddress((void**)&part, g_part);
    cudaGetSymbolAddress((void**)&ctx,  g_ctx);
    cudaGetSymbolAddress((void**)&sb,   g_sb);
    cudaGetSymbolAddress((void**)&lf,   g_lf);
    cudaGetSymbolAddress((void**)&tw,   g_tw);
    cudaGetSymbolAddress((void**)&W,    g_W);
    cudaGetSymbolAddress((void**)&sink, g_sink);

    cudaFuncSetAttribute((const void*)gemm512,
                         cudaFuncAttributeMaxDynamicSharedMemorySize, GNSTG*GSTAGE);
    cudaFuncSetAttribute((const void*)dec_route,
                         cudaFuncAttributeMaxDynamicSharedMemorySize, DR_SMEM);

    /* side stream + events for L2-prefetch overlap (graph fork/join) */
    cudaStream_t s2;
    cudaStreamCreateWithFlags(&s2, cudaStreamNonBlocking);
    cudaEvent_t eFork, eJoin;
    cudaEventCreateWithFlags(&eFork, cudaEventDisableTiming);
    cudaEventCreateWithFlags(&eJoin, cudaEventDisableTiming);

    /* one launch: convert everything to fp16 */
    cvt_all<<<928, 256>>>(X_train, enc_w1, enc_w2, X_test, Xtr, W1, W2, Xte);

    /* encoder GEMM 1 + LN1 */
    gemm512<<<dim3(HID/128, M_TRAIN/128), 512, GNSTG*GSTAGE>>>(
        Xtr, W1, enc_b1, C1, M_TRAIN, HID, DIN);
    ln_relu_h<<<M_TRAIN, 128>>>(C1, H1, ln1_g, ln1_b);

    /* FORK: prefetch first 112MB of sw_w through L2 while gemm2 runs.
       28,311,552 floats = 7,077,888 float4 -> 3456 blocks x 2048 f4. */
    cudaEventRecord(eFork, 0);
    cudaStreamWaitEvent(s2, eFork, 0);
    prefetch_l2<<<3456, 256, 0, s2>>>((const float4*)sw_w, sink, 7077888);
    cudaEventRecord(eJoin, s2);

    /* encoder GEMM 2 + LN2 + ctx (main stream, overlaps prefetch) */
    gemm512<<<dim3(HID/128, M_TRAIN/128), 512, GNSTG*GSTAGE>>>(
        H1, W2, enc_b2, C2, M_TRAIN, HID, HID);
    ln_relu_h<<<M_TRAIN, 128>>>(C2, Y2, ln2_g, ln2_b);
    col_partial_h<<<dim3(HID/512, 64), 256>>>(Y2, part);
    col_final<<<HID/256, 256>>>(part, ctx);

    /* JOIN before the big weight stream */
    cudaStreamWaitEvent(0, eJoin, 0);

    /* ALL hypernet matvecs in one launch (sw emits fp16 directly) */
    matvec_all<<<(MV_ROWS*32 + 255)/256, 256>>>(
        sw_w, sw_b, sb_w, sb_b, lf_w, lf_b, tw_w, tw_b, ctx,
        SW, sb, lf, tw);

    /* fold softmaxes */
    make_W<<<1, 512>>>(tw, lf, W);

    /* FUSED: dec GEMM + sigmoid + routing -> final output */
    dec_route<<<M_TEST/32, 512, DR_SMEM>>>(Xte, SW, sb, W, (float*)d_out);
}

// round 17
// speedup vs baseline: 1.1196x; 1.1196x over previous
#include <cuda_runtime.h>
#include <cuda_fp16.h>
#include <math.h>
#include <stdint.h>

#define M_TRAIN 4096
#define M_TEST  16384
#define DIN     128
#define HID     1024
#define NTREES  16
#define NINT    31
#define NLEAF   32
#define NCLS    10
#define NSPLIT  (NTREES*NINT)        /* 496 */
#define SW_ROWS (NTREES*NINT*DIN)    /* 63488 */
#define LF_ROWS (NTREES*NLEAF*NCLS)  /* 5120 */
#define MV_ROWS (SW_ROWS + NSPLIT + LF_ROWS + NTREES)  /* 69120 */

/* ---------------- scratch (static device memory; no allocs) -------------- */
__device__ __half g_C1[M_TRAIN*HID];
__device__ __half g_C2[M_TRAIN*HID];
__device__ __half g_H1[M_TRAIN*HID];
__device__ __half g_Y2[M_TRAIN*HID];
__device__ __half g_Xtr[M_TRAIN*DIN];
__device__ __half g_W1[HID*DIN];
__device__ __half g_W2[HID*HID];
__device__ __half g_Xte[M_TEST*DIN];
__device__ __half g_SW[SW_ROWS];
__device__ float  g_part[64*HID];
__device__ float  g_ctx[HID];
__device__ float  g_sb[NSPLIT];
__device__ float  g_lf[LF_ROWS];
__device__ float  g_tw[NTREES];

/* ------------------------------ PTX helpers ------------------------------ */
__device__ __forceinline__ uint32_t cvta_sm(const void* p) {
    return (uint32_t)__cvta_generic_to_shared(p);
}
__device__ __forceinline__ void cp16(uint32_t dst, const void* src, int sz) {
    asm volatile("cp.async.cg.shared.global [%0], [%1], 16, %2;\n"
                 :: "r"(dst), "l"(src), "r"(sz));
}
__device__ __forceinline__ void cp_commit() {
    asm volatile("cp.async.commit_group;\n");
}
__device__ __forceinline__ void ldsm4(unsigned& r0, unsigned& r1,
                                      unsigned& r2, unsigned& r3, uint32_t a) {
    asm volatile("ldmatrix.sync.aligned.m8n8.x4.shared.b16 {%0,%1,%2,%3}, [%4];"
                 : "=r"(r0), "=r"(r1), "=r"(r2), "=r"(r3) : "r"(a));
}
__device__ __forceinline__ void mma_f16(float c[4], unsigned a0, unsigned a1,
                                        unsigned a2, unsigned a3,
                                        unsigned b0, unsigned b1)
{
    asm volatile(
        "mma.sync.aligned.m16n8k16.row.col.f32.f16.f16.f32 "
        "{%0,%1,%2,%3}, {%4,%5,%6,%7}, {%8,%9}, {%0,%1,%2,%3};"
        : "+f"(c[0]), "+f"(c[1]), "+f"(c[2]), "+f"(c[3])
        : "r"(a0), "r"(a1), "r"(a2), "r"(a3), "r"(b0), "r"(b1));
}
__device__ __forceinline__ uint32_t swz(int r, int hb) {
    return (uint32_t)(r*64 + ((hb ^ ((r>>1)&3)) << 4));
}

/* ---------- ONE launch: convert all static inputs to fp16 ---------------- */
__global__ void cvt_all(const float* __restrict__ xtr, const float* __restrict__ w1,
                        const float* __restrict__ w2,  const float* __restrict__ xte,
                        __half* __restrict__ xtrh, __half* __restrict__ w1h,
                        __half* __restrict__ w2h,  __half* __restrict__ xteh)
{
    int b = blockIdx.x;
    const float* src;
    __half* dst;
    int base;
    if (b < 128)      { src = xtr; dst = xtrh; base = b; }
    else if (b < 160) { src = w1;  dst = w1h;  base = b - 128; }
    else if (b < 416) { src = w2;  dst = w2h;  base = b - 160; }
    else              { src = xte; dst = xteh; base = b - 416; }

    int i0 = base * 1024 + threadIdx.x;
    float4 v[4];
#pragma unroll
    for (int u = 0; u < 4; u++) v[u] = ((const float4*)src)[i0 + u*256];
#pragma unroll
    for (int u = 0; u < 4; u++) {
        int i = i0 + u*256;
        ((__half2*)dst)[i*2]   = __halves2half2(__float2half_rn(v[u].x),
                                                __float2half_rn(v[u].y));
        ((__half2*)dst)[i*2+1] = __halves2half2(__float2half_rn(v[u].z),
                                                __float2half_rn(v[u].w));
    }
}

/* ---- 128x128 fp16 GEMM, 512 threads, 32x32 warp tiles, fp16 out --------- */
#define GSTAGE 16384
#define GNSTG  3

__global__ void __launch_bounds__(512, 2) gemm512(
    const __half* __restrict__ Ah, const __half* __restrict__ Bh,
    const float* __restrict__ bias, __half* __restrict__ C,
    int M, int N, int K)
{
    extern __shared__ char dynsm[];
    const uint32_t smem = cvta_sm(dynsm);
    const int tid = threadIdx.x, lane = tid & 31, warp = tid >> 5;
    const int g = lane >> 2, t = lane & 3;
    const int wm = warp & 3, wn = warp >> 2;
    const int m0 = blockIdx.y * 128, n0 = blockIdx.x * 128;

    float c[2][4][4];
#pragma unroll
    for (int i = 0; i < 2; i++)
#pragma unroll
        for (int j = 0; j < 4; j++)
#pragma unroll
            for (int r = 0; r < 4; r++) c[i][j][r] = 0.f;

    const int kIters = K >> 5;

    auto load_stage = [&](int buf, int k0) {
        uint32_t sb = smem + buf * GSTAGE;
        int r = tid >> 2, hb = tid & 3;
        uint32_t so = swz(r, hb);
        cp16(sb + so,        Ah + (size_t)(m0 + r) * K + k0 + hb*8, 16);
        cp16(sb + 8192 + so, Bh + (size_t)(n0 + r) * K + k0 + hb*8, 16);
    };

    auto compute = [&](int buf) {
        uint32_t sb = smem + buf * GSTAGE;
        const int rl = lane & 15;
        const int hx = lane >> 4;
#pragma unroll
        for (int s = 0; s < 2; s++) {
            const int hb = s*2 + hx;
            unsigned bf[4][2];
#pragma unroll
            for (int j2 = 0; j2 < 2; j2++) {
                int row = wn*32 + j2*16 + rl;
                unsigned r0, r1, r2, r3;
                ldsm4(r0, r1, r2, r3, sb + 8192 + swz(row, hb));
                bf[j2*2][0]=r0; bf[j2*2][1]=r2; bf[j2*2+1][0]=r1; bf[j2*2+1][1]=r3;
            }
#pragma unroll
            for (int i = 0; i < 2; i++) {
                int row = wm*32 + i*16 + rl;
                unsigned a0,a1,a2,a3;
                ldsm4(a0,a1,a2,a3, sb + swz(row, hb));
#pragma unroll
                for (int j = 0; j < 4; j++)
                    mma_f16(c[i][j], a0,a1,a2,a3, bf[j][0], bf[j][1]);
            }
        }
    };

    load_stage(0, 0);
    cp_commit();
    load_stage(1, 32);
    cp_commit();
    for (int it = 0; it < kIters; it++) {
        if (it + 1 < kIters)
            asm volatile("cp.async.wait_group 1;\n" ::: "memory");
        else
            asm volatile("cp.async.wait_group 0;\n" ::: "memory");
        __syncthreads();
        compute(it % GNSTG);
        if (it + 2 < kIters) {
            load_stage((it+2) % GNSTG, (it+2)*32);
            cp_commit();
        }
    }

#pragma unroll
    for (int i = 0; i < 2; i++) {
        int r0 = m0 + wm*32 + i*16 + g;
#pragma unroll
        for (int j = 0; j < 4; j++) {
            int col = n0 + wn*32 + j*8 + 2*t;
            float b0 = bias[col], b1 = bias[col+1];
            *(__half2*)&C[(size_t)r0     * N + col] =
                __halves2half2(__float2half_rn(c[i][j][0] + b0),
                               __float2half_rn(c[i][j][1] + b1));
            *(__half2*)&C[(size_t)(r0+8) * N + col] =
                __halves2half2(__float2half_rn(c[i][j][2] + b0),
                               __float2half_rn(c[i][j][3] + b1));
        }
    }
}

/* ==== FUSED dec GEMM + sigmoid + softmax-fold + routing, occ 2 =========== */
/* 512 threads (2m x 8n warps, warp tile 16x64). 512 CTAs.                   */
/* smem: stages 2x34816=[0,69632) reused by trans f32[32][513]=[0,65664);    */
/*       Wsh [69632,+20480); pt [90112,+20480); tws [110592,+64).            */
#define DR_STAGE  34816
#define DR_SMEM   110656
#define TR_PITCH  513

__global__ void __launch_bounds__(512, 2) dec_route(
    const __half* __restrict__ Xte, const __half* __restrict__ SW,
    const float* __restrict__ sbias,
    const float* __restrict__ lf, const float* __restrict__ tw,
    float* __restrict__ out)
{
    extern __shared__ char dynsm[];
    const uint32_t smem = cvta_sm(dynsm);
    float* trans = (float*)dynsm;                     /* [32][513] */
    float* Wsh   = (float*)(dynsm + 69632);           /* [5120]    */
    float* pt    = (float*)(dynsm + 90112);           /* [32][16][10] */
    float* tws   = (float*)(dynsm + 110592);          /* [16]      */

    const int tid = threadIdx.x, lane = tid & 31, warp = tid >> 5;
    const int g = lane >> 2, t4 = lane & 3;
    const int wm = warp & 1, wn = warp >> 1;          /* 2(m) x 8(n) */
    const int m0 = blockIdx.x * 32;

    /* fold tree softmax (1 thread) + leaf softmaxes (1/thread) into Wsh */
    if (tid == 0) {
        float mx = -1e30f;
        for (int i = 0; i < NTREES; i++) mx = fmaxf(mx, tw[i]);
        float e[NTREES], s = 0.f;
        for (int i = 0; i < NTREES; i++) { e[i] = expf(tw[i] - mx); s += e[i]; }
        for (int i = 0; i < NTREES; i++) tws[i] = e[i] / s;
    }
    __syncthreads();
    {
        const float* L = lf + tid * NCLS;             /* tid < 512 = NTREES*NLEAF */
        float mx = -1e30f;
        for (int c = 0; c < NCLS; c++) mx = fmaxf(mx, L[c]);
        float e[NCLS], s = 0.f;
        for (int c = 0; c < NCLS; c++) { e[c] = expf(L[c] - mx); s += e[c]; }
        float scale = tws[tid >> 5] / s;
        for (int c = 0; c < NCLS; c++) Wsh[tid * NCLS + c] = e[c] * scale;
    }

    float c[8][4];
#pragma unroll
    for (int j = 0; j < 8; j++)
#pragma unroll
        for (int r = 0; r < 4; r++) c[j][r] = 0.f;

    auto load_stage = [&](int buf, int k0) {
        uint32_t sb = smem + buf * DR_STAGE;
        if (tid < 128) {
            int r = tid >> 2, hb = tid & 3;
            cp16(sb + swz(r, hb), Xte + (size_t)(m0 + r) * DIN + k0 + hb*8, 16);
        }
#pragma unroll
        for (int x = 0; x < 4; x++) {
            int ch = tid + x*512;
            int r = ch >> 2, hb = ch & 3;
            int sz = (r < NSPLIT) ? 16 : 0;
            size_t gb = (size_t)(sz ? r : 0) * DIN + k0 + hb*8;
            cp16(sb + 2048 + swz(r, hb), SW + gb, sz);
        }
    };

    auto compute = [&](int buf) {
        uint32_t sb = smem + buf * DR_STAGE;
        const int rl = lane & 15, hx = lane >> 4;
#pragma unroll
        for (int s = 0; s < 2; s++) {
            const int hb = s*2 + hx;
            unsigned a0,a1,a2,a3;
            {
                int row = wm*16 + rl;
                ldsm4(a0,a1,a2,a3, sb + swz(row, hb));
            }
            unsigned bf[8][2];
#pragma unroll
            for (int j2 = 0; j2 < 4; j2++) {
                int row = wn*64 + j2*16 + rl;
                unsigned r0,r1,r2,r3;
                ldsm4(r0,r1,r2,r3, sb + 2048 + swz(row, hb));
                bf[j2*2][0]=r0; bf[j2*2][1]=r2;
                bf[j2*2+1][0]=r1; bf[j2*2+1][1]=r3;
            }
#pragma unroll
            for (int j = 0; j < 8; j++)
                mma_f16(c[j], a0,a1,a2,a3, bf[j][0], bf[j][1]);
        }
    };

    const int kIters = DIN >> 5;   /* 4 */
    load_stage(0, 0);
    cp_commit();
    load_stage(1, 32);
    cp_commit();
    for (int it = 0; it < kIters; it++) {
        if (it + 1 < kIters)
            asm volatile("cp.async.wait_group 1;\n" ::: "memory");
        else
            asm volatile("cp.async.wait_group 0;\n" ::: "memory");
        __syncthreads();
        compute(it & 1);
        __syncthreads();
        if (it + 2 < kIters) {
            load_stage(it & 1, (it+2)*32);
            cp_commit();
        }
    }

    __syncthreads();   /* stage smem reuse -> trans */

    /* sigmoid + stage to trans[row][col] */
    {
        int r0 = wm*16 + g, r1 = r0 + 8;
#pragma unroll
        for (int j = 0; j < 8; j++) {
            int col = wn*64 + j*8 + 2*t4;
            float b0 = (col     < NSPLIT) ? sbias[col]   : 0.f;
            float b1 = (col + 1 < NSPLIT) ? sbias[col+1] : 0.f;
            trans[r0*TR_PITCH + col]   = 1.f/(1.f + __expf(-(c[j][0] + b0)));
            trans[r0*TR_PITCH + col+1] = 1.f/(1.f + __expf(-(c[j][1] + b1)));
            trans[r1*TR_PITCH + col]   = 1.f/(1.f + __expf(-(c[j][2] + b0)));
            trans[r1*TR_PITCH + col+1] = 1.f/(1.f + __expf(-(c[j][3] + b1)));
        }
    }
    __syncthreads();

    /* routing: warp = tree, lane = row */
    {
        const int t = warp, r = lane;
        const float* d = &trans[r*TR_PITCH + t*NINT];
        float acc[NCLS];
#pragma unroll
        for (int cc = 0; cc < NCLS; cc++) acc[cc] = 0.f;
#pragma unroll
        for (int l = 0; l < NLEAF; l++) {
            float p = 1.f;
#pragma unroll
            for (int dd = 0; dd < 5; dd++) {
                int node = (1 << dd) - 1 + (l >> (5 - dd));
                int go   = (l >> (4 - dd)) & 1;
                float dv = d[node];
                p *= go ? dv : (1.f - dv);
            }
            const float* w = &Wsh[(t*NLEAF + l)*NCLS];
#pragma unroll
            for (int cc = 0; cc < NCLS; cc++) acc[cc] += p * w[cc];
        }
#pragma unroll
        for (int cc = 0; cc < NCLS; cc++) pt[(r*16 + t)*NCLS + cc] = acc[cc];
    }
    __syncthreads();

    /* deterministic per-row reduction over 16 trees (320 items) */
    if (tid < 32*NCLS) {
        int r = tid / NCLS, cc = tid % NCLS;
        float s = 0.f;
#pragma unroll
        for (int t = 0; t < 16; t++) s += pt[(r*16 + t)*NCLS + cc];
        out[(size_t)(m0 + r)*NCLS + cc] = s;
    }
}

/* ------------- LayerNorm + ReLU, fp16 in -> fp16 out ---------------------- */
__global__ void ln_relu_h(const __half* __restrict__ X, __half* __restrict__ Y,
                          const float* __restrict__ gg, const float* __restrict__ bb)
{
    const int row = blockIdx.x, tid = threadIdx.x;
    const uint4 raw = ((const uint4*)(X + (size_t)row * HID))[tid];
    const __half2* h2 = (const __half2*)&raw;
    float v[8];
#pragma unroll
    for (int k = 0; k < 4; k++) {
        float2 f = __half22float2(h2[k]);
        v[k*2] = f.x; v[k*2+1] = f.y;
    }
    float s = 0.f, q = 0.f;
#pragma unroll
    for (int k = 0; k < 8; k++) { s += v[k]; q += v[k]*v[k]; }
#pragma unroll
    for (int o = 16; o; o >>= 1) {
        s += __shfl_xor_sync(0xffffffffu, s, o);
        q += __shfl_xor_sync(0xffffffffu, q, o);
    }
    __shared__ float ss[4], qs[4];
    if ((tid & 31) == 0) { ss[tid >> 5] = s; qs[tid >> 5] = q; }
    __syncthreads();
    s = ss[0]+ss[1]+ss[2]+ss[3];
    q = qs[0]+qs[1]+qs[2]+qs[3];
    float mean = s * (1.f/HID);
    float inv  = rsqrtf(q * (1.f/HID) - mean*mean + 1e-5f);
    float4 g0 = ((const float4*)gg)[tid*2],   g1 = ((const float4*)gg)[tid*2+1];
    float4 b0 = ((const float4*)bb)[tid*2],   b1 = ((const float4*)bb)[tid*2+1];
    float gv[8] = {g0.x,g0.y,g0.z,g0.w,g1.x,g1.y,g1.z,g1.w};
    float bv[8] = {b0.x,b0.y,b0.z,b0.w,b1.x,b1.y,b1.z,b1.w};
    uint4 outp;
    __half2* o2 = (__half2*)&outp;
#pragma unroll
    for (int k = 0; k < 4; k++) {
        float y0 = fmaxf((v[k*2]   - mean)*inv*gv[k*2]   + bv[k*2],   0.f);
        float y1 = fmaxf((v[k*2+1] - mean)*inv*gv[k*2+1] + bv[k*2+1], 0.f);
        o2[k] = __halves2half2(__float2half_rn(y0), __float2half_rn(y1));
    }
    ((uint4*)(Y + (size_t)row * HID))[tid] = outp;
}

/* --------------------- column mean over rows -> ctx (fp16 in) ------------ */
__global__ void col_partial_h(const __half* __restrict__ X, float* __restrict__ part)
{
    int col2  = blockIdx.x * 256 + threadIdx.x;
    int chunk = blockIdx.y;
    float2 s = make_float2(0.f, 0.f);
    int r0 = chunk * 64;
    for (int r = r0; r < r0 + 64; r++) {
        float2 f = __half22float2(((const __half2*)(X + (size_t)r * HID))[col2]);
        s.x += f.x; s.y += f.y;
    }
    *(float2*)&part[(size_t)chunk * HID + col2*2] = s;
}
__global__ void col_final(const float* __restrict__ part, float* __restrict__ ctx)
{
    int col = blockIdx.x * 256 + threadIdx.x;
    float s = 0.f;
    for (int c = 0; c < 64; c++) s += part[(size_t)c * HID + col];
    ctx[col] = s * (1.f / M_TRAIN);
}

/* ---------- ONE launch: all hypernet matvecs (warp-id dispatch) ----------- */
__global__ void matvec_all(const float* __restrict__ sw_w, const float* __restrict__ sw_b,
                           const float* __restrict__ sb_w, const float* __restrict__ sb_b,
                           const float* __restrict__ lf_w, const float* __restrict__ lf_b,
                           const float* __restrict__ tw_w, const float* __restrict__ tw_b,
                           const float* __restrict__ ctx,
                           __half* __restrict__ swh,
                           float* __restrict__ sbo, float* __restrict__ lfo,
                           float* __restrict__ two)
{
    int gw   = (blockIdx.x * blockDim.x + threadIdx.x) >> 5;
    int lane = threadIdx.x & 31;
    if (gw >= MV_ROWS) return;
    const float *W, *bias;
    int row, mode;
    if (gw < SW_ROWS)                  { W=sw_w; bias=sw_b; row=gw;                    mode=0; }
    else if (gw < SW_ROWS+NSPLIT)      { W=sb_w; bias=sb_b; row=gw-SW_ROWS;            mode=1; }
    else if (gw < SW_ROWS+NSPLIT+LF_ROWS) { W=lf_w; bias=lf_b; row=gw-SW_ROWS-NSPLIT;  mode=2; }
    else                               { W=tw_w; bias=tw_b; row=gw-SW_ROWS-NSPLIT-LF_ROWS; mode=3; }

    const float4* w4 = (const float4*)(W + (size_t)row * HID);
    const float4* c4 = (const float4*)ctx;
    float s = 0.f;
#pragma unroll
    for (int i = 0; i < 8; i++) {
        float4 a = w4[lane + 32*i];
        float4 c = __ldg(&c4[lane + 32*i]);
        s += a.x*c.x + a.y*c.y + a.z*c.z + a.w*c.w;
    }
#pragma unroll
    for (int o = 16; o; o >>= 1) s += __shfl_xor_sync(0xffffffffu, s, o);
    if (lane == 0) {
        float v = s + bias[row];
        if (mode == 0)      swh[row] = __float2half_rn(v);
        else if (mode == 1) sbo[row] = v;
        else if (mode == 2) lfo[row] = v;
        else                two[row] = v;
    }
}

/* ------------------------------- launch ---------------------------------- */
extern "C" void kernel_launch(void* const* d_in, const int* in_sizes, int n_in,
                              void* d_out, int out_size)
{
    const float* X_train = (const float*)d_in[0];
    const float* X_test  = (const float*)d_in[1];
    const float* enc_w1  = (const float*)d_in[2];
    const float* enc_b1  = (const float*)d_in[3];
    const float* ln1_g   = (const float*)d_in[4];
    const float* ln1_b   = (const float*)d_in[5];
    const float* enc_w2  = (const float*)d_in[6];
    const float* enc_b2  = (const float*)d_in[7];
    const float* ln2_g   = (const float*)d_in[8];
    const float* ln2_b   = (const float*)d_in[9];
    const float* sw_w    = (const float*)d_in[10];
    const float* sw_b    = (const float*)d_in[11];
    const float* sb_w    = (const float*)d_in[12];
    const float* sb_b    = (const float*)d_in[13];
    const float* lf_w    = (const float*)d_in[14];
    const float* lf_b    = (const float*)d_in[15];
    const float* tw_w    = (const float*)d_in[16];
    const float* tw_b    = (const float*)d_in[17];

    float *part, *ctx, *sb, *lf, *tw;
    __half *C1, *C2, *H1, *Y2, *Xtr, *W1, *W2, *Xte, *SW;
    cudaGetSymbolAddress((void**)&C1,   g_C1);
    cudaGetSymbolAddress((void**)&C2,   g_C2);
    cudaGetSymbolAddress((void**)&H1,   g_H1);
    cudaGetSymbolAddress((void**)&Y2,   g_Y2);
    cudaGetSymbolAddress((void**)&Xtr,  g_Xtr);
    cudaGetSymbolAddress((void**)&W1,   g_W1);
    cudaGetSymbolAddress((void**)&W2,   g_W2);
    cudaGetSymbolAddress((void**)&Xte,  g_Xte);
    cudaGetSymbolAddress((void**)&SW,   g_SW);
    cudaGetSymbolAddress((void**)&part, g_part);
    cudaGetSymbolAddress((void**)&ctx,  g_ctx);
    cudaGetSymbolAddress((void**)&sb,   g_sb);
    cudaGetSymbolAddress((void**)&lf,   g_lf);
    cudaGetSymbolAddress((void**)&tw,   g_tw);

    cudaFuncSetAttribute((const void*)gemm512,
                         cudaFuncAttributeMaxDynamicSharedMemorySize, GNSTG*GSTAGE);
    cudaFuncSetAttribute((const void*)dec_route,
                         cudaFuncAttributeMaxDynamicSharedMemorySize, DR_SMEM);

    /* one launch: convert everything to fp16 */
    cvt_all<<<928, 256>>>(X_train, enc_w1, enc_w2, X_test, Xtr, W1, W2, Xte);

    /* encoder: fp16 GEMMs with fp16 intermediates */
    gemm512<<<dim3(HID/128, M_TRAIN/128), 512, GNSTG*GSTAGE>>>(
        Xtr, W1, enc_b1, C1, M_TRAIN, HID, DIN);
    ln_relu_h<<<M_TRAIN, 128>>>(C1, H1, ln1_g, ln1_b);
    gemm512<<<dim3(HID/128, M_TRAIN/128), 512, GNSTG*GSTAGE>>>(
        H1, W2, enc_b2, C2, M_TRAIN, HID, HID);
    ln_relu_h<<<M_TRAIN, 128>>>(C2, Y2, ln2_g, ln2_b);

    /* ctx = mean over rows (fp16 input) */
    col_partial_h<<<dim3(HID/512, 64), 256>>>(Y2, part);
    col_final<<<HID/256, 256>>>(part, ctx);

    /* ALL hypernet matvecs in one launch (sw emits fp16 directly) */
    matvec_all<<<(MV_ROWS*32 + 255)/256, 256>>>(
        sw_w, sw_b, sb_w, sb_b, lf_w, lf_b, tw_w, tw_b, ctx,
        SW, sb, lf, tw);

    /* FUSED: dec GEMM + sigmoid + softmax-fold + routing -> final output */
    dec_route<<<M_TEST/32, 512, DR_SMEM>>>(Xte, SW, sb, lf, tw, (float*)d_out);
}